// round 2
// baseline (speedup 1.0000x reference)
#include <cuda_runtime.h>

#define NT 16384   // x rows
#define MS 4096    // sonata rows
#define NB 8       // batches
#define NH 8       // heads
#define DH 64      // head dim
#define NG 64      // slice groups
#define DM 512     // model dim
#define SCL 0.125f // D^-0.5

// ---------------- device scratch ----------------
__device__ float g_Wcomb[DM * DM];
__device__ float g_bcomb[DM];
__device__ float g_fx[(size_t)NT * DM];
__device__ float g_w[(size_t)NT * DM];        // logits, then softmax weights
__device__ float g_tokens[NB * NH * NG * DH];
__device__ float g_norms[NB * NH * NG];
__device__ float g_qkv[3 * NB * NH * NG * DH];
__device__ float g_outtok[NB * NH * NG * DH];
__device__ float g_ks[(size_t)MS * DM];
__device__ float g_vs[(size_t)MS * DM];
__device__ float g_scores[(size_t)NB * NH * NG * MS];  // 64 MB
__device__ float g_P[(size_t)NB * DM * DM];
__device__ int g_rowlist[NT], g_rowcnt[NB], g_rowstart[NB + 1], g_rowcur[NB];
__device__ int g_mlist[MS], g_mcnt[NB], g_mstart[NB + 1], g_mcur[NB];

// ---------------- setup kernels ----------------
__global__ void k_zero() {
    int i = blockIdx.x * 256 + threadIdx.x;
    if (i < NB * NH * NG * DH) g_tokens[i] = 0.f;
    if (i < NB * NH * NG) g_norms[i] = 0.f;
    if (i < NB) {
        g_rowcnt[i] = 0; g_mcnt[i] = 0;
        g_rowcur[i] = 0; g_mcur[i] = 0;
    }
}

// W_comb[c, h*64+g] = sum_d W_x[c, h*64+d] * W_slice[d, g]
__global__ void k_wcomb(const float* __restrict__ Wx, const float* __restrict__ Wsl) {
    __shared__ float s_sl[64 * 64];
    int t = threadIdx.x;
    for (int i = t; i < 4096; i += 256) s_sl[i] = Wsl[i];
    __syncthreads();
    int c = blockIdx.x;
    for (int o = t; o < 512; o += 256) {
        int h = o >> 6, g = o & 63;
        const float* wxr = Wx + (size_t)c * DM + h * 64;
        float acc = 0.f;
        for (int d = 0; d < 64; d++) acc = fmaf(wxr[d], s_sl[d * 64 + g], acc);
        g_Wcomb[(size_t)c * DM + o] = acc;
    }
}

__global__ void k_bcomb(const float* __restrict__ bx, const float* __restrict__ Wsl,
                        const float* __restrict__ bsl) {
    int o = threadIdx.x;  // 512
    int h = o >> 6, g = o & 63;
    float acc = bsl[g];
    for (int d = 0; d < 64; d++) acc = fmaf(bx[h * 64 + d], Wsl[d * 64 + g], acc);
    g_bcomb[o] = acc;
}

__global__ void k_count(const int* __restrict__ bi, const int* __restrict__ sbi) {
    int i = blockIdx.x * 256 + threadIdx.x;
    if (i < NT) atomicAdd(&g_rowcnt[bi[i]], 1);
    else if (i < NT + MS) atomicAdd(&g_mcnt[sbi[i - NT]], 1);
}

__global__ void k_prefix() {
    if (threadIdx.x == 0) {
        int s = 0;
        for (int b = 0; b < NB; b++) { g_rowstart[b] = s; s += g_rowcnt[b]; }
        g_rowstart[NB] = s;
        s = 0;
        for (int b = 0; b < NB; b++) { g_mstart[b] = s; s += g_mcnt[b]; }
        g_mstart[NB] = s;
    }
}

__global__ void k_scatter(const int* __restrict__ bi, const int* __restrict__ sbi) {
    int i = blockIdx.x * 256 + threadIdx.x;
    if (i < NT) {
        int b = bi[i];
        int p = atomicAdd(&g_rowcur[b], 1);
        g_rowlist[g_rowstart[b] + p] = i;
    } else if (i < NT + MS) {
        int j = i - NT;
        int b = sbi[j];
        int p = atomicAdd(&g_mcur[b], 1);
        g_mlist[g_mstart[b] + p] = j;
    }
}

// ---------------- front GEMM: [16384x512] @ [512x1024] -> fx | logits ----------------
__global__ void k_gemm_x(const float* __restrict__ x, const float* __restrict__ Wfx,
                         const float* __restrict__ bfx) {
    __shared__ float As[16][64];
    __shared__ float Bs[16][64];
    int t = threadIdx.x;
    int tx = t & 15, ty = t >> 4;
    int row0 = blockIdx.y * 64;
    int col0 = blockIdx.x * 64;
    bool is_fx = (col0 < DM);
    const float* Bbase = is_fx ? (Wfx + col0) : (g_Wcomb + (col0 - DM));
    int ar = t >> 2;
    int akq = (t & 3) * 4;
    int bc = t & 63;
    int bk0 = t >> 6;
    float acc[4][4] = {};
    for (int k0 = 0; k0 < DM; k0 += 16) {
        float4 a4 = *(const float4*)(x + (size_t)(row0 + ar) * DM + k0 + akq);
        As[akq + 0][ar] = a4.x; As[akq + 1][ar] = a4.y;
        As[akq + 2][ar] = a4.z; As[akq + 3][ar] = a4.w;
#pragma unroll
        for (int q = 0; q < 4; q++)
            Bs[bk0 + q * 4][bc] = Bbase[(size_t)(k0 + bk0 + q * 4) * DM + bc];
        __syncthreads();
#pragma unroll
        for (int kk = 0; kk < 16; kk++) {
            float4 av4 = *(const float4*)&As[kk][ty * 4];
            float4 bv4 = *(const float4*)&Bs[kk][tx * 4];
            float av[4] = {av4.x, av4.y, av4.z, av4.w};
            float bv[4] = {bv4.x, bv4.y, bv4.z, bv4.w};
#pragma unroll
            for (int i = 0; i < 4; i++)
#pragma unroll
                for (int j = 0; j < 4; j++) acc[i][j] = fmaf(av[i], bv[j], acc[i][j]);
        }
        __syncthreads();
    }
#pragma unroll
    for (int i = 0; i < 4; i++) {
        int r = row0 + ty * 4 + i;
#pragma unroll
        for (int j = 0; j < 4; j++) {
            int c = col0 + tx * 4 + j;
            if (is_fx) g_fx[(size_t)r * DM + c] = acc[i][j] + bfx[c];
            else g_w[(size_t)r * DM + (c - DM)] = acc[i][j] + g_bcomb[c - DM];
        }
    }
}

// per-(n,h) softmax over 64 slice logits, in place in g_w
__global__ void k_softmax(const float* __restrict__ temp) {
    int n = blockIdx.x;
    int wid = threadIdx.x >> 5, lane = threadIdx.x & 31;
    float* p = g_w + (size_t)n * DM + wid * 64;
    float it = 1.f / temp[wid];
    float v0 = p[lane] * it, v1 = p[lane + 32] * it;
    float m = fmaxf(v0, v1);
#pragma unroll
    for (int o = 16; o; o >>= 1) m = fmaxf(m, __shfl_xor_sync(0xFFFFFFFFu, m, o));
    float e0 = __expf(v0 - m), e1 = __expf(v1 - m);
    float s = e0 + e1;
#pragma unroll
    for (int o = 16; o; o >>= 1) s += __shfl_xor_sync(0xFFFFFFFFu, s, o);
    float inv = 1.f / s;
    p[lane] = e0 * inv;
    p[lane + 32] = e1 * inv;
}

// tokens[b,h,g,d] = sum_{n in b} w[n,h,g] * fx[n,h,d]; norms[b,h,g] = sum w
__global__ void k_tokens() {
    int bh = blockIdx.x;
    int b = bh >> 3, h = bh & 7;
    int cnt = g_rowcnt[b], start = g_rowstart[b];
    int c0 = (int)(((long long)cnt * blockIdx.y) >> 4);
    int c1 = (int)(((long long)cnt * (blockIdx.y + 1)) >> 4);
    int t = threadIdx.x;
    int tg = (t >> 4) * 4, td = (t & 15) * 4;
    float acc[4][4] = {};
    float nacc[4] = {};
    __shared__ float ws[8][64], fs[8][64];
    __shared__ int rid[8];
    for (int i0 = c0; i0 < c1; i0 += 8) {
        int nr = c1 - i0; if (nr > 8) nr = 8;
        if (t < nr) rid[t] = g_rowlist[start + i0 + t];
        __syncthreads();
        for (int idx = t; idx < nr * 64; idx += 256) {
            int r = idx >> 6, c = idx & 63;
            size_t off = (size_t)rid[r] * DM + h * 64 + c;
            ws[r][c] = g_w[off];
            fs[r][c] = g_fx[off];
        }
        __syncthreads();
        for (int r = 0; r < nr; r++) {
            float wv[4], fv[4];
#pragma unroll
            for (int i = 0; i < 4; i++) { wv[i] = ws[r][tg + i]; fv[i] = fs[r][td + i]; }
#pragma unroll
            for (int i = 0; i < 4; i++) {
                if (td == 0) nacc[i] += wv[i];
#pragma unroll
                for (int j = 0; j < 4; j++) acc[i][j] = fmaf(wv[i], fv[j], acc[i][j]);
            }
        }
        __syncthreads();
    }
    float* tok = g_tokens + (size_t)bh * NG * DH;
#pragma unroll
    for (int i = 0; i < 4; i++) {
#pragma unroll
        for (int j = 0; j < 4; j++) atomicAdd(&tok[(tg + i) * DH + td + j], acc[i][j]);
        if (td == 0) atomicAdd(&g_norms[bh * NG + tg + i], nacc[i]);
    }
}

// q/k/v = normalized tokens @ W + b  (per (b,h), 64x64x64)
__global__ void k_qkv(const float* __restrict__ Wq, const float* __restrict__ bq,
                      const float* __restrict__ Wk, const float* __restrict__ bk,
                      const float* __restrict__ Wv, const float* __restrict__ bv) {
    int bh = blockIdx.x, sel = blockIdx.y;
    const float* W = sel == 0 ? Wq : (sel == 1 ? Wk : Wv);
    const float* bias = sel == 0 ? bq : (sel == 1 ? bk : bv);
    __shared__ float s_a[64][65];
    __shared__ float s_b[64][64];
    int t = threadIdx.x;
    for (int i = t; i < 4096; i += 256) {
        int g = i >> 6, d = i & 63;
        s_a[g][d] = g_tokens[(size_t)bh * 4096 + i] / (g_norms[bh * 64 + g] + 1e-5f);
        s_b[g][d] = W[i];
    }
    __syncthreads();
    int tx = t & 15, ty = t >> 4;
    float acc[4][4] = {};
    for (int k = 0; k < 64; k++) {
        float av[4], bv2[4];
#pragma unroll
        for (int i = 0; i < 4; i++) av[i] = s_a[ty * 4 + i][k];
#pragma unroll
        for (int j = 0; j < 4; j++) bv2[j] = s_b[k][tx * 4 + j];
#pragma unroll
        for (int i = 0; i < 4; i++)
#pragma unroll
            for (int j = 0; j < 4; j++) acc[i][j] = fmaf(av[i], bv2[j], acc[i][j]);
    }
    float* dst = g_qkv + ((size_t)sel * 64 + bh) * 4096;
#pragma unroll
    for (int i = 0; i < 4; i++)
#pragma unroll
        for (int j = 0; j < 4; j++)
            dst[(ty * 4 + i) * 64 + tx * 4 + j] = acc[i][j] + bias[tx * 4 + j];
}

// per-(b,h) 64x64 attention: out_tok = softmax(q k^T * SCL) @ v
__global__ void k_attn() {
    int bh = blockIdx.x;
    __shared__ float s_x[64][64];  // q, then v
    __shared__ float s_k[64][64];
    __shared__ float s_s[64][64];
    int t = threadIdx.x;
    const float* q = g_qkv + (size_t)bh * 4096;
    const float* kk_ = g_qkv + (size_t)(64 + bh) * 4096;
    const float* vv = g_qkv + (size_t)(128 + bh) * 4096;
    for (int i = t; i < 4096; i += 256) { s_x[i >> 6][i & 63] = q[i]; s_k[i >> 6][i & 63] = kk_[i]; }
    __syncthreads();
    int tx = t & 15, ty = t >> 4;
    {
        float acc[4][4] = {};
        for (int d = 0; d < 64; d++) {
            float av[4], bv[4];
#pragma unroll
            for (int i = 0; i < 4; i++) av[i] = s_x[ty * 4 + i][d];
#pragma unroll
            for (int j = 0; j < 4; j++) bv[j] = s_k[tx * 4 + j][d];
#pragma unroll
            for (int i = 0; i < 4; i++)
#pragma unroll
                for (int j = 0; j < 4; j++) acc[i][j] = fmaf(av[i], bv[j], acc[i][j]);
        }
#pragma unroll
        for (int i = 0; i < 4; i++)
#pragma unroll
            for (int j = 0; j < 4; j++) s_s[ty * 4 + i][tx * 4 + j] = acc[i][j] * SCL;
    }
    __syncthreads();
    for (int i = t; i < 4096; i += 256) s_x[i >> 6][i & 63] = vv[i];  // v over q
    if (t < 64) {
        float m = -1e30f;
        for (int j = 0; j < 64; j++) m = fmaxf(m, s_s[t][j]);
        float s = 0.f;
        for (int j = 0; j < 64; j++) { float e = __expf(s_s[t][j] - m); s_s[t][j] = e; s += e; }
        float inv = 1.f / s;
        for (int j = 0; j < 64; j++) s_s[t][j] *= inv;
    }
    __syncthreads();
    float acc[4][4] = {};
    for (int k2 = 0; k2 < 64; k2++) {
        float av[4], bv[4];
#pragma unroll
        for (int i = 0; i < 4; i++) av[i] = s_s[ty * 4 + i][k2];
#pragma unroll
        for (int j = 0; j < 4; j++) bv[j] = s_x[k2][tx * 4 + j];
#pragma unroll
        for (int i = 0; i < 4; i++)
#pragma unroll
            for (int j = 0; j < 4; j++) acc[i][j] = fmaf(av[i], bv[j], acc[i][j]);
    }
#pragma unroll
    for (int i = 0; i < 4; i++)
#pragma unroll
        for (int j = 0; j < 4; j++)
            g_outtok[(size_t)bh * 4096 + (ty * 4 + i) * 64 + tx * 4 + j] = acc[i][j];
}

// sonata ks/vs projection: [32768x64] @ [64x64] + bias
__global__ void k_skv(const float* __restrict__ son,
                      const float* __restrict__ Wck, const float* __restrict__ bck,
                      const float* __restrict__ Wcv, const float* __restrict__ bcv) {
    int rt = blockIdx.x;
    int sel = blockIdx.y;
    const float* W = sel ? Wcv : Wck;
    const float* bias = sel ? bcv : bck;
    float* dst = sel ? g_vs : g_ks;
    __shared__ float s_at[64][65];
    __shared__ float s_b[64][64];
    int t = threadIdx.x;
    size_t base = (size_t)rt * 64 * 64;
    for (int i = t; i < 4096; i += 256) {
        s_at[i & 63][i >> 6] = son[base + i];
        s_b[i >> 6][i & 63] = W[i];
    }
    __syncthreads();
    int tx = t & 15, ty = t >> 4;
    float acc[4][4] = {};
    for (int k = 0; k < 64; k++) {
        float av[4], bv2[4];
#pragma unroll
        for (int i = 0; i < 4; i++) av[i] = s_at[k][ty * 4 + i];
#pragma unroll
        for (int j = 0; j < 4; j++) bv2[j] = s_b[k][tx * 4 + j];
#pragma unroll
        for (int i = 0; i < 4; i++)
#pragma unroll
            for (int j = 0; j < 4; j++) acc[i][j] = fmaf(av[i], bv2[j], acc[i][j]);
    }
#pragma unroll
    for (int i = 0; i < 4; i++)
#pragma unroll
        for (int j = 0; j < 4; j++)
            dst[base + (size_t)(ty * 4 + i) * 64 + tx * 4 + j] = acc[i][j] + bias[tx * 4 + j];
}

// per-(b,h): masked cross attention over sonata rows of batch b, out_tok += cw @ vs
__global__ void k_cross() {
    int bh = blockIdx.x, b = bh >> 3, h = bh & 7;
    int cnt = g_mcnt[b], start = g_mstart[b];
    if (cnt == 0) return;
    __shared__ float s_q[64][65];
    __shared__ float s_kv[32][64];
    __shared__ float s_cw[64][33];
    __shared__ float red[64][4];
    __shared__ int mid[32];
    int t = threadIdx.x;
    for (int i = t; i < 4096; i += 256) s_q[i >> 6][i & 63] = g_outtok[(size_t)bh * 4096 + i];
    __syncthreads();
    float* sc = g_scores + (size_t)bh * 64 * MS;
    // phase B: scores
    for (int j0 = 0; j0 < cnt; j0 += 32) {
        int nj = cnt - j0; if (nj > 32) nj = 32;
        if (t < nj) mid[t] = g_mlist[start + j0 + t];
        __syncthreads();
        for (int i = t; i < nj * 64; i += 256) {
            int r = i >> 6, c = i & 63;
            s_kv[r][c] = g_ks[(size_t)mid[r] * DM + h * 64 + c];
        }
        __syncthreads();
        int g = t & 63, jp = t >> 6;
        for (int j = jp; j < nj; j += 4) {
            float a = 0.f;
#pragma unroll 16
            for (int d = 0; d < 64; d++) a = fmaf(s_q[g][d], s_kv[j][d], a);
            sc[(size_t)g * MS + j0 + j] = a * SCL;
        }
        __syncthreads();
    }
    // phase C: row softmax over cnt entries
    {
        int g = t >> 2, part = t & 3;
        float m = -1e30f;
        for (int j = part; j < cnt; j += 4) m = fmaxf(m, sc[(size_t)g * MS + j]);
        red[g][part] = m;
        __syncthreads();
        m = fmaxf(fmaxf(red[g][0], red[g][1]), fmaxf(red[g][2], red[g][3]));
        float s = 0.f;
        for (int j = part; j < cnt; j += 4) s += __expf(sc[(size_t)g * MS + j] - m);
        __syncthreads();
        red[g][part] = s;
        __syncthreads();
        s = red[g][0] + red[g][1] + red[g][2] + red[g][3];
        float inv = 1.f / s;
        for (int j = part; j < cnt; j += 4)
            sc[(size_t)g * MS + j] = __expf(sc[(size_t)g * MS + j] - m) * inv;
    }
    __syncthreads();
    // phase D: out_tok += cw @ vs
    int tx = t & 15, ty = t >> 4;
    float acc[4][4] = {};
    for (int j0 = 0; j0 < cnt; j0 += 32) {
        int nj = cnt - j0; if (nj > 32) nj = 32;
        if (t < nj) mid[t] = g_mlist[start + j0 + t];
        __syncthreads();
        for (int i = t; i < nj * 64; i += 256) {
            int r = i >> 6, c = i & 63;
            s_kv[r][c] = g_vs[(size_t)mid[r] * DM + h * 64 + c];
        }
        for (int i = t; i < 64 * 32; i += 256) {
            int g = i >> 5, j = i & 31;
            s_cw[g][j] = (j < nj) ? sc[(size_t)g * MS + j0 + j] : 0.f;
        }
        __syncthreads();
        for (int j = 0; j < nj; j++) {
            float vvv[4];
#pragma unroll
            for (int jj = 0; jj < 4; jj++) vvv[jj] = s_kv[j][tx * 4 + jj];
#pragma unroll
            for (int i = 0; i < 4; i++) {
                float c = s_cw[ty * 4 + i][j];
#pragma unroll
                for (int jj = 0; jj < 4; jj++) acc[i][jj] = fmaf(c, vvv[jj], acc[i][jj]);
            }
        }
        __syncthreads();
    }
#pragma unroll
    for (int i = 0; i < 4; i++)
#pragma unroll
        for (int jj = 0; jj < 4; jj++) {
            size_t o = (size_t)bh * 4096 + (ty * 4 + i) * 64 + tx * 4 + jj;
            g_outtok[o] += acc[i][jj];
        }
}

// P[b, h*64+g, c] = sum_d out_tok[b,h,g,d] * W_out[h*64+d, c]
__global__ void k_P(const float* __restrict__ Wout) {
    int bh = blockIdx.x, b = bh >> 3, h = bh & 7;
    int col0 = blockIdx.y * 64;
    __shared__ float s_a[64][65];
    __shared__ float s_b[64][64];
    int t = threadIdx.x;
    for (int i = t; i < 4096; i += 256) {
        int r = i >> 6, c = i & 63;
        s_a[r][c] = g_outtok[(size_t)bh * 4096 + i];
        s_b[r][c] = Wout[(size_t)(h * 64 + r) * DM + col0 + c];
    }
    __syncthreads();
    int tx = t & 15, ty = t >> 4;
    float acc[4][4] = {};
    for (int d = 0; d < 64; d++) {
        float av[4], bv[4];
#pragma unroll
        for (int i = 0; i < 4; i++) av[i] = s_a[ty * 4 + i][d];
#pragma unroll
        for (int j = 0; j < 4; j++) bv[j] = s_b[d][tx * 4 + j];
#pragma unroll
        for (int i = 0; i < 4; i++)
#pragma unroll
            for (int j = 0; j < 4; j++) acc[i][j] = fmaf(av[i], bv[j], acc[i][j]);
    }
    float* dst = g_P + (size_t)b * DM * DM;
#pragma unroll
    for (int i = 0; i < 4; i++)
#pragma unroll
        for (int j = 0; j < 4; j++)
            dst[(size_t)(h * 64 + ty * 4 + i) * DM + col0 + tx * 4 + j] = acc[i][j];
}

// out[n, :] = w[n, :] @ P[batch(n)]   (gathered rows per batch)
__global__ void k_final(float* __restrict__ out) {
    int b = blockIdx.z;
    int cnt = g_rowcnt[b];
    int r0 = blockIdx.y * 64;
    if (r0 >= cnt) return;
    int nr = cnt - r0; if (nr > 64) nr = 64;
    int start = g_rowstart[b];
    __shared__ int rid[64];
    __shared__ float As[16][64];
    __shared__ float Bs[16][64];
    int t = threadIdx.x;
    if (t < 64) {
        int ii = t < nr ? t : nr - 1;
        rid[t] = g_rowlist[start + r0 + ii];
    }
    __syncthreads();
    int tx = t & 15, ty = t >> 4;
    int col0 = blockIdx.x * 64;
    int ar = t >> 2;
    int akq = (t & 3) * 4;
    int bc = t & 63;
    int bk0 = t >> 6;
    const float* P = g_P + (size_t)b * DM * DM;
    float acc[4][4] = {};
    for (int k0 = 0; k0 < DM; k0 += 16) {
        float4 a4 = *(const float4*)(g_w + (size_t)rid[ar] * DM + k0 + akq);
        As[akq + 0][ar] = a4.x; As[akq + 1][ar] = a4.y;
        As[akq + 2][ar] = a4.z; As[akq + 3][ar] = a4.w;
#pragma unroll
        for (int q = 0; q < 4; q++)
            Bs[bk0 + q * 4][bc] = P[(size_t)(k0 + bk0 + q * 4) * DM + col0 + bc];
        __syncthreads();
#pragma unroll
        for (int kk = 0; kk < 16; kk++) {
            float4 av4 = *(const float4*)&As[kk][ty * 4];
            float4 bv4 = *(const float4*)&Bs[kk][tx * 4];
            float av[4] = {av4.x, av4.y, av4.z, av4.w};
            float bv[4] = {bv4.x, bv4.y, bv4.z, bv4.w};
#pragma unroll
            for (int i = 0; i < 4; i++)
#pragma unroll
                for (int j = 0; j < 4; j++) acc[i][j] = fmaf(av[i], bv[j], acc[i][j]);
        }
        __syncthreads();
    }
#pragma unroll
    for (int i = 0; i < 4; i++) {
        int rl = ty * 4 + i;
        if (rl < nr) {
            size_t r = rid[rl];
#pragma unroll
            for (int j = 0; j < 4; j++)
                out[r * DM + col0 + tx * 4 + j] = acc[i][j];
        }
    }
}

extern "C" void kernel_launch(void* const* d_in, const int* in_sizes, int n_in,
                              void* d_out, int out_size) {
    const float* x    = (const float*)d_in[0];
    const int*   bi   = (const int*)d_in[1];
    const float* son  = (const float*)d_in[2];
    const int*   sbi  = (const int*)d_in[3];
    const float* temp = (const float*)d_in[4];
    const float* Wfx  = (const float*)d_in[5];
    const float* bfx  = (const float*)d_in[6];
    const float* Wx   = (const float*)d_in[7];
    const float* bx   = (const float*)d_in[8];
    const float* Wsl  = (const float*)d_in[9];
    const float* bsl  = (const float*)d_in[10];
    const float* Wq   = (const float*)d_in[11];
    const float* bq   = (const float*)d_in[12];
    const float* Wk   = (const float*)d_in[13];
    const float* bk   = (const float*)d_in[14];
    const float* Wv   = (const float*)d_in[15];
    const float* bv   = (const float*)d_in[16];
    const float* Wck  = (const float*)d_in[17];
    const float* bck  = (const float*)d_in[18];
    const float* Wcv  = (const float*)d_in[19];
    const float* bcv  = (const float*)d_in[20];
    const float* Wout = (const float*)d_in[21];
    float* out = (float*)d_out;

    k_zero<<<1024, 256>>>();
    k_wcomb<<<512, 256>>>(Wx, Wsl);
    k_bcomb<<<1, 512>>>(bx, Wsl, bsl);
    k_count<<<80, 256>>>(bi, sbi);
    k_prefix<<<1, 1>>>();
    k_scatter<<<80, 256>>>(bi, sbi);
    k_gemm_x<<<dim3(16, 256), 256>>>(x, Wfx, bfx);
    k_softmax<<<NT, 256>>>(temp);
    k_tokens<<<dim3(64, 16), 256>>>();
    k_qkv<<<dim3(64, 3), 256>>>(Wq, bq, Wk, bk, Wv, bv);
    k_attn<<<64, 256>>>();
    k_skv<<<dim3(512, 2), 256>>>(son, Wck, bck, Wcv, bcv);
    k_cross<<<64, 256>>>();
    k_P<<<dim3(64, 8), 256>>>(Wout);
    k_final<<<dim3(8, 256, 8), 256>>>(out);
}